// round 1
// baseline (speedup 1.0000x reference)
#include <cuda_runtime.h>
#include <cstdint>

// ---------------------------------------------------------------------------
// CTDExplainer: 3-layer relational GCN explainer.
//   N = 8192 nodes (6144 x + 2048 emb), D = 64, R = 3, E = 262144.
// Per layer l:
//   Hb = H @ bilin[l]                      [N,64]
//   Z  = Hb @ H^T                          [N,N]  -> output z-stack slot l
//   a  = Z[row,col] * edge_val             [E]
//   Hin = (l==0 ? H : relu(H))
//   HW[r] = Hin @ W_rel[l,r]               [N,64] x3
//   agg   = Hin @ W_root[l] + bias[l]      [N,64]
//   agg[row[e]] += HW[etype[e], col[e]] * a[e]   (segment sum)
//   H = (l<2) ? LN(agg)*g+b : agg (final output)
// Output layout assumed: [ H (N*64) | z0 (N*N) | z1 | z2 ]  fp32.
// ---------------------------------------------------------------------------

#define MAXN 8192
#define MAXE 262144
#define D 64

__device__ float g_H  [MAXN * D];
__device__ float g_Hb [MAXN * D];
__device__ float g_HW [3 * MAXN * D];
__device__ float g_agg[MAXN * D];
__device__ float g_a  [MAXE];

// ---------------- concat x|emb into H --------------------------------------
__global__ void concat_h(const float* __restrict__ x, const float* __restrict__ emb,
                         float* __restrict__ H, int nx_elems, int total_elems) {
    int i = (blockIdx.x * blockDim.x + threadIdx.x) * 4;
    if (i >= total_elems) return;
    if (i < nx_elems)
        *(float4*)(H + i) = *(const float4*)(x + i);
    else
        *(float4*)(H + i) = *(const float4*)(emb + (i - nx_elems));
}

__global__ void copy4(const float* __restrict__ src, float* __restrict__ dst, int n4) {
    int i = blockIdx.x * blockDim.x + threadIdx.x;
    if (i < n4) ((float4*)dst)[i] = ((const float4*)src)[i];
}

// ---------------- small GEMM: Out[N,64] = act(In) @ W[64,64] (+bias) -------
// 256 threads, 32 rows per block.
__global__ void ngemm64(const float* __restrict__ In, const float* __restrict__ W,
                        const float* __restrict__ bias, float* __restrict__ Out,
                        int relu) {
    __shared__ float Ws[64][64];
    __shared__ float Is[32][65];
    const int tid  = threadIdx.x;
    const int row0 = blockIdx.x * 32;

    for (int i = tid; i < 64 * 64; i += 256) Ws[i >> 6][i & 63] = W[i];
    for (int i = tid; i < 32 * 64; i += 256) {
        float v = In[(size_t)(row0 + (i >> 6)) * 64 + (i & 63)];
        Is[i >> 6][i & 63] = relu ? fmaxf(v, 0.f) : v;
    }
    __syncthreads();

    const int c  = tid & 63;
    const int r0 = tid >> 6;       // 0..3, rows r0 + 4*i
    float acc[8];
    float bv = bias ? bias[c] : 0.f;
#pragma unroll
    for (int i = 0; i < 8; i++) acc[i] = bv;
#pragma unroll
    for (int k = 0; k < 64; k++) {
        float w = Ws[k][c];
#pragma unroll
        for (int i = 0; i < 8; i++) acc[i] += Is[r0 + i * 4][k] * w;
    }
#pragma unroll
    for (int i = 0; i < 8; i++)
        Out[(size_t)(row0 + r0 + i * 4) * 64 + c] = acc[i];
}

// ---------------- big GEMM: C[N,N] = A[N,64] @ B[N,64]^T -------------------
// 128x128 tile, 256 threads, 8x8 microtile, K in two 32-chunks (32KB smem).
__global__ void __launch_bounds__(256) zgemm(const float* __restrict__ A,
                                             const float* __restrict__ B,
                                             float* __restrict__ C, int N) {
    __shared__ float As[32][128];
    __shared__ float Bs[32][128];
    const int tid = threadIdx.x;
    const int m0 = blockIdx.y * 128;
    const int n0 = blockIdx.x * 128;
    const int tx = tid & 15, ty = tid >> 4;
    const int lr = tid >> 3;            // 0..31
    const int lk = (tid & 7) * 4;       // 0..28

    float acc[8][8];
#pragma unroll
    for (int i = 0; i < 8; i++)
#pragma unroll
        for (int j = 0; j < 8; j++) acc[i][j] = 0.f;

    for (int kk = 0; kk < 64; kk += 32) {
        __syncthreads();
#pragma unroll
        for (int i = 0; i < 4; i++) {
            int m = lr + i * 32;
            float4 va = *(const float4*)(A + (size_t)(m0 + m) * 64 + kk + lk);
            As[lk + 0][m] = va.x; As[lk + 1][m] = va.y;
            As[lk + 2][m] = va.z; As[lk + 3][m] = va.w;
            float4 vb = *(const float4*)(B + (size_t)(n0 + m) * 64 + kk + lk);
            Bs[lk + 0][m] = vb.x; Bs[lk + 1][m] = vb.y;
            Bs[lk + 2][m] = vb.z; Bs[lk + 3][m] = vb.w;
        }
        __syncthreads();
#pragma unroll
        for (int k = 0; k < 32; k++) {
            float a[8], b[8];
            *(float4*)(a)     = *(const float4*)(&As[k][ty * 8]);
            *(float4*)(a + 4) = *(const float4*)(&As[k][ty * 8 + 4]);
            *(float4*)(b)     = *(const float4*)(&Bs[k][tx * 8]);
            *(float4*)(b + 4) = *(const float4*)(&Bs[k][tx * 8 + 4]);
#pragma unroll
            for (int i = 0; i < 8; i++)
#pragma unroll
                for (int j = 0; j < 8; j++) acc[i][j] += a[i] * b[j];
        }
    }
#pragma unroll
    for (int i = 0; i < 8; i++) {
        float* crow = C + (size_t)(m0 + ty * 8 + i) * N + n0 + tx * 8;
#pragma unroll
        for (int j = 0; j < 8; j += 4) {
            float4 v = make_float4(acc[i][j], acc[i][j + 1], acc[i][j + 2], acc[i][j + 3]);
            *(float4*)(crow + j) = v;
        }
    }
}

// ---------------- a = Z[row,col] * edge_val ---------------------------------
__global__ void gather_a(const float* __restrict__ Z, const int* __restrict__ row,
                         const int* __restrict__ col, const float* __restrict__ ev,
                         float* __restrict__ a, int E, int N) {
    int e = blockIdx.x * blockDim.x + threadIdx.x;
    if (e < E) a[e] = Z[(size_t)row[e] * N + col[e]] * ev[e];
}

// ---------------- scatter: agg[row] += HW[etype, col] * a -------------------
// one warp per edge, float2 vector atomics.
__global__ void scatter_msg(const float* __restrict__ HW, const int* __restrict__ row,
                            const int* __restrict__ col, const int* __restrict__ et,
                            const float* __restrict__ a, float* __restrict__ agg,
                            int E, int N) {
    int warp = (blockIdx.x * blockDim.x + threadIdx.x) >> 5;
    int lane = threadIdx.x & 31;
    if (warp >= E) return;
    int r = row[warp], c = col[warp], t = et[warp];
    float av = a[warp];
    float2 m = ((const float2*)(HW + ((size_t)t * N + c) * 64))[lane];
    float2 val = make_float2(m.x * av, m.y * av);
#if __CUDA_ARCH__ >= 900
    atomicAdd(((float2*)(agg + (size_t)r * 64)) + lane, val);
#else
    atomicAdd(agg + (size_t)r * 64 + 2 * lane,     val.x);
    atomicAdd(agg + (size_t)r * 64 + 2 * lane + 1, val.y);
#endif
}

// ---------------- layernorm over last dim (64) ------------------------------
__global__ void ln_kernel(const float* __restrict__ In, const float* __restrict__ g,
                          const float* __restrict__ b, float* __restrict__ Out, int N) {
    int warp = (blockIdx.x * blockDim.x + threadIdx.x) >> 5;
    int lane = threadIdx.x & 31;
    if (warp >= N) return;
    float2 v = ((const float2*)(In + (size_t)warp * 64))[lane];
    float s = v.x + v.y;
#pragma unroll
    for (int o = 16; o; o >>= 1) s += __shfl_xor_sync(0xffffffffu, s, o);
    float mu = s * (1.f / 64.f);
    float dx = v.x - mu, dy = v.y - mu;
    float q = dx * dx + dy * dy;
#pragma unroll
    for (int o = 16; o; o >>= 1) q += __shfl_xor_sync(0xffffffffu, q, o);
    float inv = rsqrtf(q * (1.f / 64.f) + 1e-5f);
    float2 gg = ((const float2*)g)[lane];
    float2 bb = ((const float2*)b)[lane];
    float2 o2 = make_float2(dx * inv * gg.x + bb.x, dy * inv * gg.y + bb.y);
    ((float2*)(Out + (size_t)warp * 64))[lane] = o2;
}

// ---------------------------------------------------------------------------
extern "C" void kernel_launch(void* const* d_in, const int* in_sizes, int n_in,
                              void* d_out, int out_size) {
    const float* x       = (const float*)d_in[0];
    const float* emb     = (const float*)d_in[1];
    const float* bilin   = (const float*)d_in[2];
    const float* eval    = (const float*)d_in[3];
    const float* W_root  = (const float*)d_in[4];
    const float* W_rel   = (const float*)d_in[5];
    const float* bias    = (const float*)d_in[6];
    const float* ln_g    = (const float*)d_in[7];
    const float* ln_b    = (const float*)d_in[8];
    const int*   erow    = (const int*)d_in[9];
    const int*   ecol    = (const int*)d_in[10];
    const int*   etype   = (const int*)d_in[11];

    const int NX = in_sizes[0] / D;
    const int NE = in_sizes[1] / D;
    const int N  = NX + NE;
    const int E  = in_sizes[3];

    float* out  = (float*)d_out;
    float* Hout = out;
    float* Zbase = out + (size_t)N * D;

    float *H, *Hb, *HW, *agg, *a;
    cudaGetSymbolAddress((void**)&H,   g_H);
    cudaGetSymbolAddress((void**)&Hb,  g_Hb);
    cudaGetSymbolAddress((void**)&HW,  g_HW);
    cudaGetSymbolAddress((void**)&agg, g_agg);
    cudaGetSymbolAddress((void**)&a,   g_a);

    // H = concat(x, emb)
    {
        int total = N * D;
        int blocks = (total / 4 + 255) / 256;
        concat_h<<<blocks, 256>>>(x, emb, H, NX * D, total);
    }

    dim3 zgrid(N / 128, N / 128);
    const int ngemm_blocks = N / 32;
    const int gather_blocks = (E + 255) / 256;
    const int scatter_blocks = (E * 32 + 255) / 256;
    const int ln_blocks = (N * 32 + 255) / 256;

    for (int l = 0; l < 3; l++) {
        float* Zl = Zbase + (size_t)l * N * N;
        int relu = (l > 0) ? 1 : 0;

        // Hb = H @ bilin[l]   (no activation on H for the bilinear branch)
        ngemm64<<<ngemm_blocks, 256>>>(H, bilin + (size_t)l * D * D, nullptr, Hb, 0);
        // Z = Hb @ H^T
        zgemm<<<zgrid, 256>>>(Hb, H, Zl, N);
        // a = Z[row,col] * edge_val
        gather_a<<<gather_blocks, 256>>>(Zl, erow, ecol, eval, a, E, N);
        // HW[r] = act(H) @ W_rel[l][r]
        for (int r = 0; r < 3; r++)
            ngemm64<<<ngemm_blocks, 256>>>(H, W_rel + ((size_t)(l * 3 + r)) * D * D,
                                           nullptr, HW + (size_t)r * N * D, relu);
        // agg = act(H) @ W_root[l] + bias[l]
        ngemm64<<<ngemm_blocks, 256>>>(H, W_root + (size_t)l * D * D,
                                       bias + (size_t)l * D, agg, relu);
        // agg[row] += HW[etype, col] * a
        scatter_msg<<<scatter_blocks, 256>>>(HW, erow, ecol, etype, a, agg, E, N);

        if (l < 2) {
            ln_kernel<<<ln_blocks, 256>>>(agg, ln_g + (size_t)l * D,
                                          ln_b + (size_t)l * D, H, N);
        } else {
            copy4<<<(N * D / 4 + 255) / 256, 256>>>(agg, Hout, N * D / 4);
        }
    }
}

// round 3
// speedup vs baseline: 1.5744x; 1.5744x over previous
#include <cuda_runtime.h>
#include <cuda_fp16.h>
#include <cstdint>

// ---------------------------------------------------------------------------
// CTDExplainer: 3-layer relational GCN explainer. N=8192, D=64, R=3, E=262144.
// Round 3: Z = Hb @ H^T via mma.sync m16n8k16 fp16 HMMA (baseline PTX, no
// tcgen05 — ptxas target is compute_103 without the 'a' feature set).
// Accuracy: fp16 hi/lo 3-term split (hi*hi + hi*lo + lo*hi), err ~2^-22.
// Output layout: [ H (N*64) | z0 (N*N) | z1 | z2 ]  fp32.
// ---------------------------------------------------------------------------

#define MAXN 8192
#define MAXE 262144
#define D 64

__device__ float g_H   [MAXN * D];
__device__ float g_Hb  [MAXN * D];
__device__ float g_HW  [3 * MAXN * D];
__device__ float g_agg [MAXN * D];
__device__ float g_a   [MAXE];
// hi/lo fp16 splits, stored as uint2 (4 halfs) for 8B-aligned access
__device__ uint2 g_hbhi[MAXN * D / 4];
__device__ uint2 g_hblo[MAXN * D / 4];
__device__ uint2 g_hhi [MAXN * D / 4];
__device__ uint2 g_hlo [MAXN * D / 4];

// ---------------- concat x|emb into H --------------------------------------
__global__ void concat_h(const float* __restrict__ x, const float* __restrict__ emb,
                         float* __restrict__ H, int nx_elems, int total_elems) {
    int i = (blockIdx.x * blockDim.x + threadIdx.x) * 4;
    if (i >= total_elems) return;
    if (i < nx_elems)
        *(float4*)(H + i) = *(const float4*)(x + i);
    else
        *(float4*)(H + i) = *(const float4*)(emb + (i - nx_elems));
}

__global__ void copy4(const float* __restrict__ src, float* __restrict__ dst, int n4) {
    int i = blockIdx.x * blockDim.x + threadIdx.x;
    if (i < n4) ((float4*)dst)[i] = ((const float4*)src)[i];
}

// ---------------- fp16 hi/lo split ------------------------------------------
__global__ void split_f16(const float4* __restrict__ in, uint2* __restrict__ hi,
                          uint2* __restrict__ lo, int n4) {
    int i = blockIdx.x * blockDim.x + threadIdx.x;
    if (i >= n4) return;
    float4 x = in[i];
    __half hx = __float2half_rn(x.x), hy = __float2half_rn(x.y);
    __half hz = __float2half_rn(x.z), hw = __float2half_rn(x.w);
    __half lx = __float2half_rn(x.x - __half2float(hx));
    __half ly = __float2half_rn(x.y - __half2float(hy));
    __half lz = __float2half_rn(x.z - __half2float(hz));
    __half lw = __float2half_rn(x.w - __half2float(hw));
    __half2 h01 = __halves2half2(hx, hy), h23 = __halves2half2(hz, hw);
    __half2 l01 = __halves2half2(lx, ly), l23 = __halves2half2(lz, lw);
    uint2 ho, lu;
    ho.x = *(uint32_t*)&h01; ho.y = *(uint32_t*)&h23;
    lu.x = *(uint32_t*)&l01; lu.y = *(uint32_t*)&l23;
    hi[i] = ho; lo[i] = lu;
}

// ---------------- small GEMM: Out[N,64] = act(In) @ W[64,64] (+bias) -------
__global__ void ngemm64(const float* __restrict__ In, const float* __restrict__ W,
                        const float* __restrict__ bias, float* __restrict__ Out,
                        int relu) {
    __shared__ float Ws[64][64];
    __shared__ float Is[32][65];
    const int tid  = threadIdx.x;
    const int row0 = blockIdx.x * 32;

    for (int i = tid; i < 64 * 64; i += 256) Ws[i >> 6][i & 63] = W[i];
    for (int i = tid; i < 32 * 64; i += 256) {
        float v = In[(size_t)(row0 + (i >> 6)) * 64 + (i & 63)];
        Is[i >> 6][i & 63] = relu ? fmaxf(v, 0.f) : v;
    }
    __syncthreads();

    const int c  = tid & 63;
    const int r0 = tid >> 6;
    float acc[8];
    float bv = bias ? bias[c] : 0.f;
#pragma unroll
    for (int i = 0; i < 8; i++) acc[i] = bv;
#pragma unroll
    for (int k = 0; k < 64; k++) {
        float w = Ws[k][c];
#pragma unroll
        for (int i = 0; i < 8; i++) acc[i] += Is[r0 + i * 4][k] * w;
    }
#pragma unroll
    for (int i = 0; i < 8; i++)
        Out[(size_t)(row0 + r0 + i * 4) * 64 + c] = acc[i];
}

// ---------------- HMMA big GEMM: C[N,N] = A[N,64] @ B[N,64]^T ---------------
// 128x128 CTA tile, 256 thr (8 warps: 4m x 2n), warp tile 32x64.
// 3 fp16 terms: Ahi*Bhi + Ahi*Blo + Alo*Bhi, fp32 accumulate.
// SMEM rows padded to 72 halfs (144B) -> conflict-free ldmatrix.
#define SROW 72
#define TILEB (128 * SROW * 2)      // 18432 B per tile
#define SM_TOT (4 * TILEB)          // 73728 B

__device__ __forceinline__ uint32_t smem_u32(const void* p) {
    uint32_t a;
    asm("{ .reg .u64 t; cvta.to.shared.u64 t, %1; cvt.u32.u64 %0, t; }" : "=r"(a) : "l"(p));
    return a;
}
__device__ __forceinline__ void ldm_x4(uint32_t& r0, uint32_t& r1, uint32_t& r2,
                                       uint32_t& r3, uint32_t addr) {
    asm volatile("ldmatrix.sync.aligned.m8n8.x4.shared.b16 {%0,%1,%2,%3}, [%4];"
                 : "=r"(r0), "=r"(r1), "=r"(r2), "=r"(r3) : "r"(addr));
}
__device__ __forceinline__ void mma16816(float* c, uint32_t a0, uint32_t a1,
                                         uint32_t a2, uint32_t a3,
                                         uint32_t b0, uint32_t b1) {
    asm volatile(
        "mma.sync.aligned.m16n8k16.row.col.f32.f16.f16.f32 "
        "{%0,%1,%2,%3}, {%4,%5,%6,%7}, {%8,%9}, {%0,%1,%2,%3};"
        : "+f"(c[0]), "+f"(c[1]), "+f"(c[2]), "+f"(c[3])
        : "r"(a0), "r"(a1), "r"(a2), "r"(a3), "r"(b0), "r"(b1));
}

__global__ void __launch_bounds__(256) zgemm_mma(
    const __half* __restrict__ Ahi, const __half* __restrict__ Alo,
    const __half* __restrict__ Bhi, const __half* __restrict__ Blo,
    float* __restrict__ C, int N) {
    extern __shared__ __align__(16) char smem[];
    const int tid = threadIdx.x;
    const int m0 = blockIdx.y * 128, n0 = blockIdx.x * 128;

    // cooperative tile loads (each array: 128 rows x 64 halfs)
    {
        const int row = tid >> 1;
        const int c   = (tid & 1) * 32;            // half-column
        const __half* gA0 = Ahi + (size_t)(m0 + row) * 64 + c;
        const __half* gA1 = Alo + (size_t)(m0 + row) * 64 + c;
        const __half* gB0 = Bhi + (size_t)(n0 + row) * 64 + c;
        const __half* gB1 = Blo + (size_t)(n0 + row) * 64 + c;
        char* s = smem + row * 144 + c * 2;
#pragma unroll
        for (int i = 0; i < 4; i++) {
            *(uint4*)(s + 0 * TILEB + i * 16) = *(const uint4*)(gA0 + i * 8);
            *(uint4*)(s + 1 * TILEB + i * 16) = *(const uint4*)(gA1 + i * 8);
            *(uint4*)(s + 2 * TILEB + i * 16) = *(const uint4*)(gB0 + i * 8);
            *(uint4*)(s + 3 * TILEB + i * 16) = *(const uint4*)(gB1 + i * 8);
        }
    }
    __syncthreads();

    const int lane = tid & 31;
    const int wid  = tid >> 5;
    const int wm   = (wid & 3) * 32;   // warp m offset in tile
    const int wn   = (wid >> 2) * 64;  // warp n offset in tile
    const uint32_t sb = smem_u32(smem);

    // lane-relative ldmatrix addresses
    const int a_r = lane & 15;
    const int a_c = (lane >> 4) << 3;                       // 0 or 8 (k)
    const int b_r = (lane & 7) + (((lane >> 4) & 1) << 3);  // n row within 16
    const int b_c = ((lane >> 3) & 1) << 3;                 // 0 or 8 (k)

    float acc[16][4];                   // [mi*8+ni][4]
#pragma unroll
    for (int i = 0; i < 16; i++)
#pragma unroll
        for (int j = 0; j < 4; j++) acc[i][j] = 0.f;

    const int aoff[3] = {0, 0, TILEB};
    const int boff[3] = {2 * TILEB, 3 * TILEB, 2 * TILEB};

#pragma unroll
    for (int t = 0; t < 3; t++) {
        const uint32_t abase = sb + aoff[t] + (wm + a_r) * 144 + a_c * 2;
        const uint32_t bbase = sb + boff[t] + (wn + b_r) * 144 + b_c * 2;
#pragma unroll
        for (int kc = 0; kc < 4; kc++) {
            uint32_t A0[4], A1[4];
            ldm_x4(A0[0], A0[1], A0[2], A0[3], abase + kc * 32);
            ldm_x4(A1[0], A1[1], A1[2], A1[3], abase + 16 * 144 + kc * 32);
            uint32_t Bf[8][2];          // [ni][b0,b1]
#pragma unroll
            for (int nt = 0; nt < 4; nt++) {
                uint32_t r0, r1, r2, r3;
                ldm_x4(r0, r1, r2, r3, bbase + nt * 16 * 144 + kc * 32);
                Bf[2 * nt][0] = r0;  Bf[2 * nt][1] = r1;
                Bf[2 * nt + 1][0] = r2;  Bf[2 * nt + 1][1] = r3;
            }
#pragma unroll
            for (int ni = 0; ni < 8; ni++) {
                mma16816(acc[ni],     A0[0], A0[1], A0[2], A0[3], Bf[ni][0], Bf[ni][1]);
                mma16816(acc[8 + ni], A1[0], A1[1], A1[2], A1[3], Bf[ni][0], Bf[ni][1]);
            }
        }
    }

    // epilogue: c0,c1 -> (row, col..col+1); c2,c3 -> (row+8, ...)
    const int er = lane >> 2;
    const int ec = (lane & 3) * 2;
#pragma unroll
    for (int mi = 0; mi < 2; mi++)
#pragma unroll
        for (int ni = 0; ni < 8; ni++) {
            float* f = acc[mi * 8 + ni];
            size_t r = (size_t)(m0 + wm + mi * 16 + er);
            int col = n0 + wn + ni * 8 + ec;
            *(float2*)(C + r * N + col)       = make_float2(f[0], f[1]);
            *(float2*)(C + (r + 8) * N + col) = make_float2(f[2], f[3]);
        }
}

// ---------------- a = Z[row,col] * edge_val ---------------------------------
__global__ void gather_a(const float* __restrict__ Z, const int* __restrict__ row,
                         const int* __restrict__ col, const float* __restrict__ ev,
                         float* __restrict__ a, int E, int N) {
    int e = blockIdx.x * blockDim.x + threadIdx.x;
    if (e < E) a[e] = Z[(size_t)row[e] * N + col[e]] * ev[e];
}

// ---------------- scatter: agg[row] += HW[etype, col] * a -------------------
__global__ void scatter_msg(const float* __restrict__ HW, const int* __restrict__ row,
                            const int* __restrict__ col, const int* __restrict__ et,
                            const float* __restrict__ a, float* __restrict__ agg,
                            int E, int N) {
    int warp = (blockIdx.x * blockDim.x + threadIdx.x) >> 5;
    int lane = threadIdx.x & 31;
    if (warp >= E) return;
    int r = row[warp], c = col[warp], t = et[warp];
    float av = a[warp];
    float2 m = ((const float2*)(HW + ((size_t)t * N + c) * 64))[lane];
    float2 val = make_float2(m.x * av, m.y * av);
#if __CUDA_ARCH__ >= 900
    atomicAdd(((float2*)(agg + (size_t)r * 64)) + lane, val);
#else
    atomicAdd(agg + (size_t)r * 64 + 2 * lane,     val.x);
    atomicAdd(agg + (size_t)r * 64 + 2 * lane + 1, val.y);
#endif
}

// ---------------- layernorm over last dim (64) ------------------------------
__global__ void ln_kernel(const float* __restrict__ In, const float* __restrict__ g,
                          const float* __restrict__ b, float* __restrict__ Out, int N) {
    int warp = (blockIdx.x * blockDim.x + threadIdx.x) >> 5;
    int lane = threadIdx.x & 31;
    if (warp >= N) return;
    float2 v = ((const float2*)(In + (size_t)warp * 64))[lane];
    float s = v.x + v.y;
#pragma unroll
    for (int o = 16; o; o >>= 1) s += __shfl_xor_sync(0xffffffffu, s, o);
    float mu = s * (1.f / 64.f);
    float dx = v.x - mu, dy = v.y - mu;
    float q = dx * dx + dy * dy;
#pragma unroll
    for (int o = 16; o; o >>= 1) q += __shfl_xor_sync(0xffffffffu, q, o);
    float inv = rsqrtf(q * (1.f / 64.f) + 1e-5f);
    float2 gg = ((const float2*)g)[lane];
    float2 bb = ((const float2*)b)[lane];
    float2 o2 = make_float2(dx * inv * gg.x + bb.x, dy * inv * gg.y + bb.y);
    ((float2*)(Out + (size_t)warp * 64))[lane] = o2;
}

// ---------------------------------------------------------------------------
extern "C" void kernel_launch(void* const* d_in, const int* in_sizes, int n_in,
                              void* d_out, int out_size) {
    const float* x       = (const float*)d_in[0];
    const float* emb     = (const float*)d_in[1];
    const float* bilin   = (const float*)d_in[2];
    const float* eval    = (const float*)d_in[3];
    const float* W_root  = (const float*)d_in[4];
    const float* W_rel   = (const float*)d_in[5];
    const float* bias    = (const float*)d_in[6];
    const float* ln_g    = (const float*)d_in[7];
    const float* ln_b    = (const float*)d_in[8];
    const int*   erow    = (const int*)d_in[9];
    const int*   ecol    = (const int*)d_in[10];
    const int*   etype   = (const int*)d_in[11];

    const int NX = in_sizes[0] / D;
    const int NE = in_sizes[1] / D;
    const int N  = NX + NE;
    const int E  = in_sizes[3];

    float* out  = (float*)d_out;
    float* Hout = out;
    float* Zbase = out + (size_t)N * D;

    float *H, *Hb, *HW, *agg, *a;
    uint2 *hbhi, *hblo, *hhi, *hlo;
    cudaGetSymbolAddress((void**)&H,    g_H);
    cudaGetSymbolAddress((void**)&Hb,   g_Hb);
    cudaGetSymbolAddress((void**)&HW,   g_HW);
    cudaGetSymbolAddress((void**)&agg,  g_agg);
    cudaGetSymbolAddress((void**)&a,    g_a);
    cudaGetSymbolAddress((void**)&hbhi, g_hbhi);
    cudaGetSymbolAddress((void**)&hblo, g_hblo);
    cudaGetSymbolAddress((void**)&hhi,  g_hhi);
    cudaGetSymbolAddress((void**)&hlo,  g_hlo);

    cudaFuncSetAttribute(zgemm_mma, cudaFuncAttributeMaxDynamicSharedMemorySize, SM_TOT);

    // H = concat(x, emb)
    {
        int total = N * D;
        int blocks = (total / 4 + 255) / 256;
        concat_h<<<blocks, 256>>>(x, emb, H, NX * D, total);
    }

    dim3 zgrid(N / 128, N / 128);
    const int ngemm_blocks   = N / 32;
    const int split_blocks   = (N * D / 4 + 255) / 256;
    const int gather_blocks  = (E + 255) / 256;
    const int scatter_blocks = (E * 32 + 255) / 256;
    const int ln_blocks      = (N * 32 + 255) / 256;

    for (int l = 0; l < 3; l++) {
        float* Zl = Zbase + (size_t)l * N * N;
        int relu = (l > 0) ? 1 : 0;

        // Hb = H @ bilin[l]
        ngemm64<<<ngemm_blocks, 256>>>(H, bilin + (size_t)l * D * D, nullptr, Hb, 0);
        // fp16 hi/lo splits of Hb and H
        split_f16<<<split_blocks, 256>>>((const float4*)Hb, hbhi, hblo, N * D / 4);
        split_f16<<<split_blocks, 256>>>((const float4*)H,  hhi,  hlo,  N * D / 4);
        // Z = Hb @ H^T via HMMA 3-term
        zgemm_mma<<<zgrid, 256, SM_TOT>>>((const __half*)hbhi, (const __half*)hblo,
                                          (const __half*)hhi,  (const __half*)hlo, Zl, N);
        // a = Z[row,col] * edge_val
        gather_a<<<gather_blocks, 256>>>(Zl, erow, ecol, eval, a, E, N);
        // HW[r] = act(H) @ W_rel[l][r]
        for (int r = 0; r < 3; r++)
            ngemm64<<<ngemm_blocks, 256>>>(H, W_rel + ((size_t)(l * 3 + r)) * D * D,
                                           nullptr, HW + (size_t)r * N * D, relu);
        // agg = act(H) @ W_root[l] + bias[l]
        ngemm64<<<ngemm_blocks, 256>>>(H, W_root + (size_t)l * D * D,
                                       bias + (size_t)l * D, agg, relu);
        // agg[row] += HW[etype, col] * a
        scatter_msg<<<scatter_blocks, 256>>>(HW, erow, ecol, etype, a, agg, E, N);

        if (l < 2) {
            ln_kernel<<<ln_blocks, 256>>>(agg, ln_g + (size_t)l * D,
                                          ln_b + (size_t)l * D, H, N);
        } else {
            copy4<<<(N * D / 4 + 255) / 256, 256>>>(agg, Hout, N * D / 4);
        }
    }
}

// round 4
// speedup vs baseline: 1.9431x; 1.2342x over previous
#include <cuda_runtime.h>
#include <cuda_fp16.h>
#include <cstdint>

// ---------------------------------------------------------------------------
// CTDExplainer: 3-layer relational GCN explainer. N=8192, D=64, R=3, E=262144.
// Round 4: swizzled-smem HMMA zgemm (2 CTAs/SM), fused per-layer small kernels
// (ngemm_all emits Hb hi/lo fp16 + HW + agg in one pass; edge gather+scatter
// fused; fp16 split fused into concat / layernorm epilogues).
// Output layout: [ H (N*64) | z0 (N*N) | z1 | z2 ]  fp32.
// ---------------------------------------------------------------------------

#define MAXN 8192
#define MAXE 262144
#define D 64

__device__ float g_H   [MAXN * D];
__device__ float g_HW  [3 * MAXN * D];
__device__ float g_agg [MAXN * D];
__device__ uint2 g_hbhi[MAXN * D / 4];   // fp16 hi/lo splits (4 halfs per uint2)
__device__ uint2 g_hblo[MAXN * D / 4];
__device__ uint2 g_hhi [MAXN * D / 4];
__device__ uint2 g_hlo [MAXN * D / 4];

// ---------------- fp16 split helpers ----------------------------------------
__device__ __forceinline__ void split4(float4 x, uint2& ho, uint2& lu) {
    __half hx = __float2half_rn(x.x), hy = __float2half_rn(x.y);
    __half hz = __float2half_rn(x.z), hw = __float2half_rn(x.w);
    __half lx = __float2half_rn(x.x - __half2float(hx));
    __half ly = __float2half_rn(x.y - __half2float(hy));
    __half lz = __float2half_rn(x.z - __half2float(hz));
    __half lw = __float2half_rn(x.w - __half2float(hw));
    __half2 h01 = __halves2half2(hx, hy), h23 = __halves2half2(hz, hw);
    __half2 l01 = __halves2half2(lx, ly), l23 = __halves2half2(lz, lw);
    ho.x = *(uint32_t*)&h01; ho.y = *(uint32_t*)&h23;
    lu.x = *(uint32_t*)&l01; lu.y = *(uint32_t*)&l23;
}

// ---------------- concat x|emb into H (+ fp16 split) ------------------------
__global__ void concat_split(const float* __restrict__ x, const float* __restrict__ emb,
                             float* __restrict__ H, uint2* __restrict__ hhi,
                             uint2* __restrict__ hlo, int nx_elems, int total_elems) {
    int i = (blockIdx.x * blockDim.x + threadIdx.x) * 4;
    if (i >= total_elems) return;
    float4 v = (i < nx_elems) ? *(const float4*)(x + i)
                              : *(const float4*)(emb + (i - nx_elems));
    *(float4*)(H + i) = v;
    uint2 ho, lu;
    split4(v, ho, lu);
    hhi[i >> 2] = ho; hlo[i >> 2] = lu;
}

// ---------------- fused per-layer small GEMMs --------------------------------
// One block = 32 rows. Computes, reading act variants of H once from smem:
//   o=0: Hb = H @ bilin         -> hbhi/hblo (fp16 hi/lo, direct)
//   o=1..3: HW[o-1] = act(H) @ W_rel[o-1]
//   o=4: agg = act(H) @ W_root + bias
__global__ void __launch_bounds__(256) ngemm_all(
    const float* __restrict__ H, const float* __restrict__ bilin,
    const float* __restrict__ Wrel, const float* __restrict__ Wroot,
    const float* __restrict__ bias, __half* __restrict__ hbhi,
    __half* __restrict__ hblo, float* __restrict__ HW,
    float* __restrict__ agg, int relu, int N) {
    __shared__ float Ws[64][64];
    __shared__ float Is[32][65];
    const int tid  = threadIdx.x;
    const int row0 = blockIdx.x * 32;

    for (int i = tid; i < 32 * 64; i += 256)
        Is[i >> 6][i & 63] = H[(size_t)(row0 + (i >> 6)) * 64 + (i & 63)];

    const int c  = tid & 63;
    const int r0 = tid >> 6;

    for (int o = 0; o < 5; o++) {
        const float* W = (o == 0) ? bilin : (o < 4) ? Wrel + (size_t)(o - 1) * 4096 : Wroot;
        __syncthreads();
        for (int i = tid; i < 64 * 64; i += 256) Ws[i >> 6][i & 63] = W[i];
        __syncthreads();

        float acc[8];
        float bv = (o == 4) ? bias[c] : 0.f;
#pragma unroll
        for (int i = 0; i < 8; i++) acc[i] = bv;
        const int act = (o > 0) ? relu : 0;
#pragma unroll
        for (int k = 0; k < 64; k++) {
            float w = Ws[k][c];
#pragma unroll
            for (int i = 0; i < 8; i++) {
                float v = Is[r0 + i * 4][k];
                if (act) v = fmaxf(v, 0.f);
                acc[i] += v * w;
            }
        }
        if (o == 0) {
#pragma unroll
            for (int i = 0; i < 8; i++) {
                size_t idx = (size_t)(row0 + r0 + i * 4) * 64 + c;
                __half h = __float2half_rn(acc[i]);
                hbhi[idx] = h;
                hblo[idx] = __float2half_rn(acc[i] - __half2float(h));
            }
        } else if (o < 4) {
            float* Out = HW + (size_t)(o - 1) * N * 64;
#pragma unroll
            for (int i = 0; i < 8; i++)
                Out[(size_t)(row0 + r0 + i * 4) * 64 + c] = acc[i];
        } else {
#pragma unroll
            for (int i = 0; i < 8; i++)
                agg[(size_t)(row0 + r0 + i * 4) * 64 + c] = acc[i];
        }
    }
}

// ---------------- HMMA big GEMM: C[N,N] = A[N,64] @ B[N,64]^T ---------------
// 128x128 CTA tile, 256 thr (8 warps: 4m x 2n), warp tile 32x64.
// 3 fp16 terms: Ahi*Bhi + Ahi*Blo + Alo*Bhi, fp32 accumulate.
// SMEM: 128B rows, XOR-swizzled 16B units -> 16KB/tile, 64KB total, 2 CTA/SM.
#define TILEB 16384
#define SM_TOT (4 * TILEB)

__device__ __forceinline__ uint32_t smem_u32(const void* p) {
    uint32_t a;
    asm("{ .reg .u64 t; cvta.to.shared.u64 t, %1; cvt.u32.u64 %0, t; }" : "=r"(a) : "l"(p));
    return a;
}
__device__ __forceinline__ void ldm_x4(uint32_t& r0, uint32_t& r1, uint32_t& r2,
                                       uint32_t& r3, uint32_t addr) {
    asm volatile("ldmatrix.sync.aligned.m8n8.x4.shared.b16 {%0,%1,%2,%3}, [%4];"
                 : "=r"(r0), "=r"(r1), "=r"(r2), "=r"(r3) : "r"(addr));
}
__device__ __forceinline__ void mma16816(float* c, uint32_t a0, uint32_t a1,
                                         uint32_t a2, uint32_t a3,
                                         uint32_t b0, uint32_t b1) {
    asm volatile(
        "mma.sync.aligned.m16n8k16.row.col.f32.f16.f16.f32 "
        "{%0,%1,%2,%3}, {%4,%5,%6,%7}, {%8,%9}, {%0,%1,%2,%3};"
        : "+f"(c[0]), "+f"(c[1]), "+f"(c[2]), "+f"(c[3])
        : "r"(a0), "r"(a1), "r"(a2), "r"(a3), "r"(b0), "r"(b1));
}

__global__ void __launch_bounds__(256, 2) zgemm_mma(
    const __half* __restrict__ Ahi, const __half* __restrict__ Alo,
    const __half* __restrict__ Bhi, const __half* __restrict__ Blo,
    float* __restrict__ C, int N) {
    extern __shared__ __align__(16) char smem[];
    const int tid = threadIdx.x;
    const int m0 = blockIdx.y * 128, n0 = blockIdx.x * 128;

    // cooperative tile loads: 128 rows x 64 halfs (128B) per array, swizzled.
    {
        const int row = tid >> 1;
        const int cu  = (tid & 1) * 4;          // first 16B unit (0 or 4)
        const int r7  = row & 7;
        const __half* gA0 = Ahi + (size_t)(m0 + row) * 64 + (tid & 1) * 32;
        const __half* gA1 = Alo + (size_t)(m0 + row) * 64 + (tid & 1) * 32;
        const __half* gB0 = Bhi + (size_t)(n0 + row) * 64 + (tid & 1) * 32;
        const __half* gB1 = Blo + (size_t)(n0 + row) * 64 + (tid & 1) * 32;
        char* s = smem + row * 128;
#pragma unroll
        for (int i = 0; i < 4; i++) {
            int off = ((cu + i) ^ r7) << 4;
            *(uint4*)(s + 0 * TILEB + off) = *(const uint4*)(gA0 + i * 8);
            *(uint4*)(s + 1 * TILEB + off) = *(const uint4*)(gA1 + i * 8);
            *(uint4*)(s + 2 * TILEB + off) = *(const uint4*)(gB0 + i * 8);
            *(uint4*)(s + 3 * TILEB + off) = *(const uint4*)(gB1 + i * 8);
        }
    }
    __syncthreads();

    const int lane = tid & 31;
    const int wid  = tid >> 5;
    const int wm   = (wid & 3) * 32;   // warp m offset
    const int wn   = (wid >> 2) * 64;  // warp n offset
    const uint32_t sb = smem_u32(smem);

    // A: lanes 0-15 rows 0-15 (k-unit au=0), lanes 16-31 same rows (au=1)
    const int a_row = wm + (lane & 15);
    const int a_r7  = a_row & 7;
    const int au    = lane >> 4;
    const uint32_t abase_row = sb + a_row * 128;
    // B: lanes 0-7 n-rows 0-7 u0; 8-15 rows 0-7 u1; 16-23 rows 8-15 u0; 24-31 rows 8-15 u1
    const int b_row = wn + (lane & 7) + (((lane >> 4) & 1) << 3);
    const int b_r7  = b_row & 7;
    const int bu    = (lane >> 3) & 1;
    const uint32_t bbase_row = sb + b_row * 128;

    float acc[16][4];
#pragma unroll
    for (int i = 0; i < 16; i++)
#pragma unroll
        for (int j = 0; j < 4; j++) acc[i][j] = 0.f;

    const int aoff[3] = {0, 0, TILEB};
    const int boff[3] = {2 * TILEB, 3 * TILEB, 2 * TILEB};

#pragma unroll
    for (int t = 0; t < 3; t++) {
#pragma unroll
        for (int kc = 0; kc < 4; kc++) {
            const uint32_t aaddr = abase_row + aoff[t] + ((((kc << 1) + au) ^ a_r7) << 4);
            const uint32_t baddr = bbase_row + boff[t] + ((((kc << 1) + bu) ^ b_r7) << 4);
            uint32_t A0[4], A1[4];
            ldm_x4(A0[0], A0[1], A0[2], A0[3], aaddr);
            ldm_x4(A1[0], A1[1], A1[2], A1[3], aaddr + 16 * 128);
            uint32_t Bf[8][2];
#pragma unroll
            for (int nt = 0; nt < 4; nt++) {
                uint32_t r0, r1, r2, r3;
                ldm_x4(r0, r1, r2, r3, baddr + nt * 16 * 128);
                Bf[2 * nt][0] = r0;  Bf[2 * nt][1] = r1;
                Bf[2 * nt + 1][0] = r2;  Bf[2 * nt + 1][1] = r3;
            }
#pragma unroll
            for (int ni = 0; ni < 8; ni++) {
                mma16816(acc[ni],     A0[0], A0[1], A0[2], A0[3], Bf[ni][0], Bf[ni][1]);
                mma16816(acc[8 + ni], A1[0], A1[1], A1[2], A1[3], Bf[ni][0], Bf[ni][1]);
            }
        }
    }

    const int er = lane >> 2;
    const int ec = (lane & 3) * 2;
#pragma unroll
    for (int mi = 0; mi < 2; mi++)
#pragma unroll
        for (int ni = 0; ni < 8; ni++) {
            float* f = acc[mi * 8 + ni];
            size_t r = (size_t)(m0 + wm + mi * 16 + er);
            int col = n0 + wn + ni * 8 + ec;
            *(float2*)(C + r * N + col)       = make_float2(f[0], f[1]);
            *(float2*)(C + (r + 8) * N + col) = make_float2(f[2], f[3]);
        }
}

// ---------------- fused edge gather + scatter --------------------------------
// one warp per edge: a = Z[row,col]*ev; agg[row] += HW[etype,col] * a
__global__ void edge_fused(const float* __restrict__ Z, const float* __restrict__ HW,
                           const int* __restrict__ row, const int* __restrict__ col,
                           const int* __restrict__ et, const float* __restrict__ ev,
                           float* __restrict__ agg, int E, int N) {
    int e = (blockIdx.x * blockDim.x + threadIdx.x) >> 5;
    int lane = threadIdx.x & 31;
    if (e >= E) return;
    int r = row[e], c = col[e], t = et[e];
    float av = Z[(size_t)r * N + c] * ev[e];
    float2 m = ((const float2*)(HW + ((size_t)t * N + c) * 64))[lane];
    float2 val = make_float2(m.x * av, m.y * av);
#if __CUDA_ARCH__ >= 900
    atomicAdd(((float2*)(agg + (size_t)r * 64)) + lane, val);
#else
    atomicAdd(agg + (size_t)r * 64 + 2 * lane,     val.x);
    atomicAdd(agg + (size_t)r * 64 + 2 * lane + 1, val.y);
#endif
}

// ---------------- layernorm (+ fp16 split of output) ------------------------
__global__ void ln_split(const float* __restrict__ In, const float* __restrict__ g,
                         const float* __restrict__ b, float* __restrict__ Out,
                         __half2* __restrict__ hhi, __half2* __restrict__ hlo, int N) {
    int wrow = (blockIdx.x * blockDim.x + threadIdx.x) >> 5;
    int lane = threadIdx.x & 31;
    if (wrow >= N) return;
    float2 v = ((const float2*)(In + (size_t)wrow * 64))[lane];
    float s = v.x + v.y;
#pragma unroll
    for (int o = 16; o; o >>= 1) s += __shfl_xor_sync(0xffffffffu, s, o);
    float mu = s * (1.f / 64.f);
    float dx = v.x - mu, dy = v.y - mu;
    float q = dx * dx + dy * dy;
#pragma unroll
    for (int o = 16; o; o >>= 1) q += __shfl_xor_sync(0xffffffffu, q, o);
    float inv = rsqrtf(q * (1.f / 64.f) + 1e-5f);
    float2 gg = ((const float2*)g)[lane];
    float2 bb = ((const float2*)b)[lane];
    float ox = dx * inv * gg.x + bb.x;
    float oy = dy * inv * gg.y + bb.y;
    ((float2*)(Out + (size_t)wrow * 64))[lane] = make_float2(ox, oy);
    __half hx = __float2half_rn(ox), hy = __float2half_rn(oy);
    hhi[wrow * 32 + lane] = __halves2half2(hx, hy);
    hlo[wrow * 32 + lane] = __halves2half2(__float2half_rn(ox - __half2float(hx)),
                                           __float2half_rn(oy - __half2float(hy)));
}

// ---------------------------------------------------------------------------
extern "C" void kernel_launch(void* const* d_in, const int* in_sizes, int n_in,
                              void* d_out, int out_size) {
    const float* x       = (const float*)d_in[0];
    const float* emb     = (const float*)d_in[1];
    const float* bilin   = (const float*)d_in[2];
    const float* eval    = (const float*)d_in[3];
    const float* W_root  = (const float*)d_in[4];
    const float* W_rel   = (const float*)d_in[5];
    const float* bias    = (const float*)d_in[6];
    const float* ln_g    = (const float*)d_in[7];
    const float* ln_b    = (const float*)d_in[8];
    const int*   erow    = (const int*)d_in[9];
    const int*   ecol    = (const int*)d_in[10];
    const int*   etype   = (const int*)d_in[11];

    const int NX = in_sizes[0] / D;
    const int NE = in_sizes[1] / D;
    const int N  = NX + NE;
    const int E  = in_sizes[3];

    float* out   = (float*)d_out;
    float* Hout  = out;
    float* Zbase = out + (size_t)N * D;

    float *H, *HW, *agg;
    uint2 *hbhi, *hblo, *hhi, *hlo;
    cudaGetSymbolAddress((void**)&H,    g_H);
    cudaGetSymbolAddress((void**)&HW,   g_HW);
    cudaGetSymbolAddress((void**)&agg,  g_agg);
    cudaGetSymbolAddress((void**)&hbhi, g_hbhi);
    cudaGetSymbolAddress((void**)&hblo, g_hblo);
    cudaGetSymbolAddress((void**)&hhi,  g_hhi);
    cudaGetSymbolAddress((void**)&hlo,  g_hlo);

    cudaFuncSetAttribute(zgemm_mma, cudaFuncAttributeMaxDynamicSharedMemorySize, SM_TOT);

    // H = concat(x, emb) + fp16 split
    {
        int total = N * D;
        int blocks = (total / 4 + 255) / 256;
        concat_split<<<blocks, 256>>>(x, emb, H, hhi, hlo, NX * D, total);
    }

    dim3 zgrid(N / 128, N / 128);
    const int ngemm_blocks = N / 32;
    const int edge_blocks  = (E * 32 + 255) / 256;
    const int ln_blocks    = (N * 32 + 255) / 256;

    for (int l = 0; l < 3; l++) {
        float* Zl   = Zbase + (size_t)l * N * N;
        float* aggl = (l < 2) ? agg : Hout;
        int relu = (l > 0) ? 1 : 0;

        // Hb(hi/lo) + HW[0..2] + agg in one pass over H
        ngemm_all<<<ngemm_blocks, 256>>>(H, bilin + (size_t)l * D * D,
                                         W_rel + (size_t)l * 3 * D * D,
                                         W_root + (size_t)l * D * D,
                                         bias + (size_t)l * D,
                                         (__half*)hbhi, (__half*)hblo,
                                         HW, aggl, relu, N);
        // Z = Hb @ H^T via HMMA 3-term
        zgemm_mma<<<zgrid, 256, SM_TOT>>>((const __half*)hbhi, (const __half*)hblo,
                                          (const __half*)hhi,  (const __half*)hlo, Zl, N);
        // agg[row] += HW[etype, col] * (Z[row,col] * ev)
        edge_fused<<<edge_blocks, 256>>>(Zl, HW, erow, ecol, etype, eval, aggl, E, N);

        if (l < 2)
            ln_split<<<ln_blocks, 256>>>(aggl, ln_g + (size_t)l * D, ln_b + (size_t)l * D,
                                         H, (__half2*)hhi, (__half2*)hlo, N);
    }
}

// round 5
// speedup vs baseline: 2.1975x; 1.1309x over previous
#include <cuda_runtime.h>
#include <cuda_fp16.h>
#include <cstdint>

// ---------------------------------------------------------------------------
// CTDExplainer: 3-layer relational GCN explainer. N=8192, D=64, R=3, E=262144.
// Round 5: v4 vector reduction atomics in edge kernel (16 lanes/edge),
// ngemm_all parallelized over outputs (grid.y=5), zgemm fragment loads merged
// across the 3 fp16 split terms (LDSM 18->12 per k-chunk).
// Output layout: [ H (N*64) | z0 (N*N) | z1 | z2 ]  fp32.
// ---------------------------------------------------------------------------

#define MAXN 8192
#define MAXE 262144
#define D 64

__device__ float g_H   [MAXN * D];
__device__ float g_HW  [3 * MAXN * D];
__device__ float g_agg [MAXN * D];
__device__ uint2 g_hbhi[MAXN * D / 4];   // fp16 hi/lo splits (4 halfs per uint2)
__device__ uint2 g_hblo[MAXN * D / 4];
__device__ uint2 g_hhi [MAXN * D / 4];
__device__ uint2 g_hlo [MAXN * D / 4];

// ---------------- fp16 split helpers ----------------------------------------
__device__ __forceinline__ void split4(float4 x, uint2& ho, uint2& lu) {
    __half hx = __float2half_rn(x.x), hy = __float2half_rn(x.y);
    __half hz = __float2half_rn(x.z), hw = __float2half_rn(x.w);
    __half lx = __float2half_rn(x.x - __half2float(hx));
    __half ly = __float2half_rn(x.y - __half2float(hy));
    __half lz = __float2half_rn(x.z - __half2float(hz));
    __half lw = __float2half_rn(x.w - __half2float(hw));
    __half2 h01 = __halves2half2(hx, hy), h23 = __halves2half2(hz, hw);
    __half2 l01 = __halves2half2(lx, ly), l23 = __halves2half2(lz, lw);
    ho.x = *(uint32_t*)&h01; ho.y = *(uint32_t*)&h23;
    lu.x = *(uint32_t*)&l01; lu.y = *(uint32_t*)&l23;
}

// ---------------- concat x|emb into H (+ fp16 split) ------------------------
__global__ void concat_split(const float* __restrict__ x, const float* __restrict__ emb,
                             float* __restrict__ H, uint2* __restrict__ hhi,
                             uint2* __restrict__ hlo, int nx_elems, int total_elems) {
    int i = (blockIdx.x * blockDim.x + threadIdx.x) * 4;
    if (i >= total_elems) return;
    float4 v = (i < nx_elems) ? *(const float4*)(x + i)
                              : *(const float4*)(emb + (i - nx_elems));
    *(float4*)(H + i) = v;
    uint2 ho, lu;
    split4(v, ho, lu);
    hhi[i >> 2] = ho; hlo[i >> 2] = lu;
}

// ---------------- fused per-layer small GEMMs (one output per block) --------
// grid = (N/32, 5). blockIdx.y selects:
//   0: Hb = H @ bilin        -> hbhi/hblo (fp16 hi/lo)
//   1..3: HW[y-1] = act(H) @ W_rel[y-1]
//   4: agg = act(H) @ W_root + bias
__global__ void __launch_bounds__(256) ngemm_all(
    const float* __restrict__ H, const float* __restrict__ bilin,
    const float* __restrict__ Wrel, const float* __restrict__ Wroot,
    const float* __restrict__ bias, __half* __restrict__ hbhi,
    __half* __restrict__ hblo, float* __restrict__ HW,
    float* __restrict__ agg, int relu, int N) {
    __shared__ float Ws[64][64];
    __shared__ float Is[32][65];
    const int tid  = threadIdx.x;
    const int row0 = blockIdx.x * 32;
    const int o    = blockIdx.y;

    const float* W = (o == 0) ? bilin : (o < 4) ? Wrel + (size_t)(o - 1) * 4096 : Wroot;
    const int act = (o > 0) ? relu : 0;

    for (int i = tid; i < 64 * 64; i += 256) Ws[i >> 6][i & 63] = W[i];
    for (int i = tid; i < 32 * 64; i += 256) {
        float v = H[(size_t)(row0 + (i >> 6)) * 64 + (i & 63)];
        Is[i >> 6][i & 63] = act ? fmaxf(v, 0.f) : v;
    }
    __syncthreads();

    const int c  = tid & 63;
    const int r0 = tid >> 6;
    float acc[8];
    float bv = (o == 4) ? bias[c] : 0.f;
#pragma unroll
    for (int i = 0; i < 8; i++) acc[i] = bv;
#pragma unroll
    for (int k = 0; k < 64; k++) {
        float w = Ws[k][c];
#pragma unroll
        for (int i = 0; i < 8; i++) acc[i] += Is[r0 + i * 4][k] * w;
    }

    if (o == 0) {
#pragma unroll
        for (int i = 0; i < 8; i++) {
            size_t idx = (size_t)(row0 + r0 + i * 4) * 64 + c;
            __half h = __float2half_rn(acc[i]);
            hbhi[idx] = h;
            hblo[idx] = __float2half_rn(acc[i] - __half2float(h));
        }
    } else if (o < 4) {
        float* Out = HW + (size_t)(o - 1) * N * 64;
#pragma unroll
        for (int i = 0; i < 8; i++)
            Out[(size_t)(row0 + r0 + i * 4) * 64 + c] = acc[i];
    } else {
#pragma unroll
        for (int i = 0; i < 8; i++)
            agg[(size_t)(row0 + r0 + i * 4) * 64 + c] = acc[i];
    }
}

// ---------------- HMMA big GEMM: C[N,N] = A[N,64] @ B[N,64]^T ---------------
// 128x128 CTA tile, 256 thr (8 warps: 4m x 2n), warp tile 32x64.
// 3 fp16 terms accumulate into one fp32 acc; fragments loaded ONCE per kc.
// SMEM: 128B rows, XOR-swizzled 16B units -> 16KB/tile, 64KB total, 2 CTA/SM.
#define TILEB 16384
#define SM_TOT (4 * TILEB)

__device__ __forceinline__ uint32_t smem_u32(const void* p) {
    uint32_t a;
    asm("{ .reg .u64 t; cvta.to.shared.u64 t, %1; cvt.u32.u64 %0, t; }" : "=r"(a) : "l"(p));
    return a;
}
__device__ __forceinline__ void ldm_x4(uint32_t& r0, uint32_t& r1, uint32_t& r2,
                                       uint32_t& r3, uint32_t addr) {
    asm volatile("ldmatrix.sync.aligned.m8n8.x4.shared.b16 {%0,%1,%2,%3}, [%4];"
                 : "=r"(r0), "=r"(r1), "=r"(r2), "=r"(r3) : "r"(addr));
}
__device__ __forceinline__ void mma16816(float* c, const uint32_t* a,
                                         uint32_t b0, uint32_t b1) {
    asm volatile(
        "mma.sync.aligned.m16n8k16.row.col.f32.f16.f16.f32 "
        "{%0,%1,%2,%3}, {%4,%5,%6,%7}, {%8,%9}, {%0,%1,%2,%3};"
        : "+f"(c[0]), "+f"(c[1]), "+f"(c[2]), "+f"(c[3])
        : "r"(a[0]), "r"(a[1]), "r"(a[2]), "r"(a[3]), "r"(b0), "r"(b1));
}

__global__ void __launch_bounds__(256, 2) zgemm_mma(
    const __half* __restrict__ Ahi, const __half* __restrict__ Alo,
    const __half* __restrict__ Bhi, const __half* __restrict__ Blo,
    float* __restrict__ C, int N) {
    extern __shared__ __align__(16) char smem[];
    const int tid = threadIdx.x;
    const int m0 = blockIdx.y * 128, n0 = blockIdx.x * 128;

    // cooperative tile loads: 128 rows x 64 halfs (128B) per array, swizzled.
    {
        const int row = tid >> 1;
        const int cu  = (tid & 1) * 4;
        const int r7  = row & 7;
        const __half* gA0 = Ahi + (size_t)(m0 + row) * 64 + (tid & 1) * 32;
        const __half* gA1 = Alo + (size_t)(m0 + row) * 64 + (tid & 1) * 32;
        const __half* gB0 = Bhi + (size_t)(n0 + row) * 64 + (tid & 1) * 32;
        const __half* gB1 = Blo + (size_t)(n0 + row) * 64 + (tid & 1) * 32;
        char* s = smem + row * 128;
#pragma unroll
        for (int i = 0; i < 4; i++) {
            int off = ((cu + i) ^ r7) << 4;
            *(uint4*)(s + 0 * TILEB + off) = *(const uint4*)(gA0 + i * 8);
            *(uint4*)(s + 1 * TILEB + off) = *(const uint4*)(gA1 + i * 8);
            *(uint4*)(s + 2 * TILEB + off) = *(const uint4*)(gB0 + i * 8);
            *(uint4*)(s + 3 * TILEB + off) = *(const uint4*)(gB1 + i * 8);
        }
    }
    __syncthreads();

    const int lane = tid & 31;
    const int wid  = tid >> 5;
    const int wm   = (wid & 3) * 32;
    const int wn   = (wid >> 2) * 64;
    const uint32_t sb = smem_u32(smem);

    const int a_row = wm + (lane & 15);
    const int a_r7  = a_row & 7;
    const int au    = lane >> 4;
    const uint32_t abase_row = sb + a_row * 128;
    const int b_row = wn + (lane & 7) + (((lane >> 4) & 1) << 3);
    const int b_r7  = b_row & 7;
    const int bu    = (lane >> 3) & 1;
    const uint32_t bbase_row = sb + b_row * 128;

    float acc[16][4];
#pragma unroll
    for (int i = 0; i < 16; i++)
#pragma unroll
        for (int j = 0; j < 4; j++) acc[i][j] = 0.f;

#pragma unroll
    for (int kc = 0; kc < 4; kc++) {
        const uint32_t aoffk = ((((kc << 1) + au) ^ a_r7) << 4);
        const uint32_t boffk = ((((kc << 1) + bu) ^ b_r7) << 4);
        uint32_t Ah[8], Al[8];
        ldm_x4(Ah[0], Ah[1], Ah[2], Ah[3], abase_row + aoffk);
        ldm_x4(Ah[4], Ah[5], Ah[6], Ah[7], abase_row + aoffk + 16 * 128);
        ldm_x4(Al[0], Al[1], Al[2], Al[3], abase_row + TILEB + aoffk);
        ldm_x4(Al[4], Al[5], Al[6], Al[7], abase_row + TILEB + aoffk + 16 * 128);
#pragma unroll
        for (int nt = 0; nt < 4; nt++) {
            uint32_t bh[4], bl[4];
            ldm_x4(bh[0], bh[1], bh[2], bh[3],
                   bbase_row + 2 * TILEB + boffk + nt * 16 * 128);
            ldm_x4(bl[0], bl[1], bl[2], bl[3],
                   bbase_row + 3 * TILEB + boffk + nt * 16 * 128);
            const int n0i = 2 * nt;
            // term Ahi*Bhi (4 distinct accs)
            mma16816(acc[n0i],         Ah,     bh[0], bh[1]);
            mma16816(acc[n0i + 1],     Ah,     bh[2], bh[3]);
            mma16816(acc[8 + n0i],     Ah + 4, bh[0], bh[1]);
            mma16816(acc[8 + n0i + 1], Ah + 4, bh[2], bh[3]);
            // term Ahi*Blo
            mma16816(acc[n0i],         Ah,     bl[0], bl[1]);
            mma16816(acc[n0i + 1],     Ah,     bl[2], bl[3]);
            mma16816(acc[8 + n0i],     Ah + 4, bl[0], bl[1]);
            mma16816(acc[8 + n0i + 1], Ah + 4, bl[2], bl[3]);
            // term Alo*Bhi
            mma16816(acc[n0i],         Al,     bh[0], bh[1]);
            mma16816(acc[n0i + 1],     Al,     bh[2], bh[3]);
            mma16816(acc[8 + n0i],     Al + 4, bh[0], bh[1]);
            mma16816(acc[8 + n0i + 1], Al + 4, bh[2], bh[3]);
        }
    }

    const int er = lane >> 2;
    const int ec = (lane & 3) * 2;
#pragma unroll
    for (int mi = 0; mi < 2; mi++)
#pragma unroll
        for (int ni = 0; ni < 8; ni++) {
            float* f = acc[mi * 8 + ni];
            size_t r = (size_t)(m0 + wm + mi * 16 + er);
            int col = n0 + wn + ni * 8 + ec;
            *(float2*)(C + r * N + col)       = make_float2(f[0], f[1]);
            *(float2*)(C + (r + 8) * N + col) = make_float2(f[2], f[3]);
        }
}

// ---------------- fused edge gather + scatter (16 lanes/edge, v4 red) -------
__global__ void edge_fused(const float* __restrict__ Z, const float* __restrict__ HW,
                           const int* __restrict__ row, const int* __restrict__ col,
                           const int* __restrict__ et, const float* __restrict__ ev,
                           float* __restrict__ agg, int E, int N) {
    int gi  = blockIdx.x * blockDim.x + threadIdx.x;
    int e   = gi >> 4;
    int sub = threadIdx.x & 15;
    if (e >= E) return;
    int r = row[e], c = col[e], t = et[e];
    float av = Z[(size_t)r * N + c] * ev[e];
    float4 m = ((const float4*)(HW + ((size_t)t * N + c) * 64))[sub];
    float* dst = agg + (size_t)r * 64 + sub * 4;
    asm volatile("red.global.add.v4.f32 [%0], {%1, %2, %3, %4};"
                 :: "l"(dst), "f"(m.x * av), "f"(m.y * av),
                    "f"(m.z * av), "f"(m.w * av) : "memory");
}

// ---------------- layernorm (+ fp16 split of output) ------------------------
__global__ void ln_split(const float* __restrict__ In, const float* __restrict__ g,
                         const float* __restrict__ b, float* __restrict__ Out,
                         __half2* __restrict__ hhi, __half2* __restrict__ hlo, int N) {
    int wrow = (blockIdx.x * blockDim.x + threadIdx.x) >> 5;
    int lane = threadIdx.x & 31;
    if (wrow >= N) return;
    float2 v = ((const float2*)(In + (size_t)wrow * 64))[lane];
    float s = v.x + v.y;
#pragma unroll
    for (int o = 16; o; o >>= 1) s += __shfl_xor_sync(0xffffffffu, s, o);
    float mu = s * (1.f / 64.f);
    float dx = v.x - mu, dy = v.y - mu;
    float q = dx * dx + dy * dy;
#pragma unroll
    for (int o = 16; o; o >>= 1) q += __shfl_xor_sync(0xffffffffu, q, o);
    float inv = rsqrtf(q * (1.f / 64.f) + 1e-5f);
    float2 gg = ((const float2*)g)[lane];
    float2 bb = ((const float2*)b)[lane];
    float ox = dx * inv * gg.x + bb.x;
    float oy = dy * inv * gg.y + bb.y;
    ((float2*)(Out + (size_t)wrow * 64))[lane] = make_float2(ox, oy);
    __half hx = __float2half_rn(ox), hy = __float2half_rn(oy);
    hhi[wrow * 32 + lane] = __halves2half2(hx, hy);
    hlo[wrow * 32 + lane] = __halves2half2(__float2half_rn(ox - __half2float(hx)),
                                           __float2half_rn(oy - __half2float(hy)));
}

// ---------------------------------------------------------------------------
extern "C" void kernel_launch(void* const* d_in, const int* in_sizes, int n_in,
                              void* d_out, int out_size) {
    const float* x       = (const float*)d_in[0];
    const float* emb     = (const float*)d_in[1];
    const float* bilin   = (const float*)d_in[2];
    const float* eval    = (const float*)d_in[3];
    const float* W_root  = (const float*)d_in[4];
    const float* W_rel   = (const float*)d_in[5];
    const float* bias    = (const float*)d_in[6];
    const float* ln_g    = (const float*)d_in[7];
    const float* ln_b    = (const float*)d_in[8];
    const int*   erow    = (const int*)d_in[9];
    const int*   ecol    = (const int*)d_in[10];
    const int*   etype   = (const int*)d_in[11];

    const int NX = in_sizes[0] / D;
    const int NE = in_sizes[1] / D;
    const int N  = NX + NE;
    const int E  = in_sizes[3];

    float* out   = (float*)d_out;
    float* Hout  = out;
    float* Zbase = out + (size_t)N * D;

    float *H, *HW, *agg;
    uint2 *hbhi, *hblo, *hhi, *hlo;
    cudaGetSymbolAddress((void**)&H,    g_H);
    cudaGetSymbolAddress((void**)&HW,   g_HW);
    cudaGetSymbolAddress((void**)&agg,  g_agg);
    cudaGetSymbolAddress((void**)&hbhi, g_hbhi);
    cudaGetSymbolAddress((void**)&hblo, g_hblo);
    cudaGetSymbolAddress((void**)&hhi,  g_hhi);
    cudaGetSymbolAddress((void**)&hlo,  g_hlo);

    cudaFuncSetAttribute(zgemm_mma, cudaFuncAttributeMaxDynamicSharedMemorySize, SM_TOT);

    // H = concat(x, emb) + fp16 split
    {
        int total = N * D;
        int blocks = (total / 4 + 255) / 256;
        concat_split<<<blocks, 256>>>(x, emb, H, hhi, hlo, NX * D, total);
    }

    dim3 zgrid(N / 128, N / 128);
    dim3 ngrid(N / 32, 5);
    const int edge_blocks = (E * 16 + 255) / 256;
    const int ln_blocks   = (N * 32 + 255) / 256;

    for (int l = 0; l < 3; l++) {
        float* Zl   = Zbase + (size_t)l * N * N;
        float* aggl = (l < 2) ? agg : Hout;
        int relu = (l > 0) ? 1 : 0;

        // Hb(hi/lo) + HW[0..2] + agg (parallel over outputs)
        ngemm_all<<<ngrid, 256>>>(H, bilin + (size_t)l * D * D,
                                  W_rel + (size_t)l * 3 * D * D,
                                  W_root + (size_t)l * D * D,
                                  bias + (size_t)l * D,
                                  (__half*)hbhi, (__half*)hblo,
                                  HW, aggl, relu, N);
        // Z = Hb @ H^T via HMMA 3-term (fragments shared across terms)
        zgemm_mma<<<zgrid, 256, SM_TOT>>>((const __half*)hbhi, (const __half*)hblo,
                                          (const __half*)hhi,  (const __half*)hlo, Zl, N);
        // agg[row] += HW[etype, col] * (Z[row,col] * ev)
        edge_fused<<<edge_blocks, 256>>>(Zl, HW, erow, ecol, etype, eval, aggl, E, N);

        if (l < 2)
            ln_split<<<ln_blocks, 256>>>(aggl, ln_g + (size_t)l * D, ln_b + (size_t)l * D,
                                         H, (__half2*)hhi, (__half2*)hlo, N);
    }
}

// round 6
// speedup vs baseline: 2.4139x; 1.0985x over previous
#include <cuda_runtime.h>
#include <cuda_fp16.h>
#include <cstdint>

// ---------------------------------------------------------------------------
// CTDExplainer: 3-layer relational GCN explainer. N=8192, D=64, R=3, E=262144.
// Round 6: 2-term fp16 split for Z = Hb @ H^T:
//   Z ~= Hbhi*Hhi^T + Hblo*Hhi^T   (drops Hb*Hlo correction, ~1.5e-4 rel err)
// -> 33% fewer HMMAs (the measured bottleneck), B-side lo tile eliminated.
// Output layout: [ H (N*64) | z0 (N*N) | z1 | z2 ]  fp32.
// ---------------------------------------------------------------------------

#define MAXN 8192
#define MAXE 262144
#define D 64

__device__ float g_H   [MAXN * D];
__device__ float g_HW  [3 * MAXN * D];
__device__ float g_agg [MAXN * D];
__device__ uint2 g_hbhi[MAXN * D / 4];   // fp16 splits (4 halfs per uint2)
__device__ uint2 g_hblo[MAXN * D / 4];
__device__ uint2 g_hhi [MAXN * D / 4];

// ---------------- concat x|emb into H (+ fp16 hi) ----------------------------
__global__ void concat_split(const float* __restrict__ x, const float* __restrict__ emb,
                             float* __restrict__ H, uint2* __restrict__ hhi,
                             int nx_elems, int total_elems) {
    int i = (blockIdx.x * blockDim.x + threadIdx.x) * 4;
    if (i >= total_elems) return;
    float4 v = (i < nx_elems) ? *(const float4*)(x + i)
                              : *(const float4*)(emb + (i - nx_elems));
    *(float4*)(H + i) = v;
    __half2 h01 = __halves2half2(__float2half_rn(v.x), __float2half_rn(v.y));
    __half2 h23 = __halves2half2(__float2half_rn(v.z), __float2half_rn(v.w));
    uint2 ho;
    ho.x = *(uint32_t*)&h01; ho.y = *(uint32_t*)&h23;
    hhi[i >> 2] = ho;
}

// ---------------- fused per-layer small GEMMs (one output per block) --------
// grid = (N/32, 5). blockIdx.y selects:
//   0: Hb = H @ bilin        -> hbhi/hblo (fp16 hi/lo)
//   1..3: HW[y-1] = act(H) @ W_rel[y-1]
//   4: agg = act(H) @ W_root + bias
__global__ void __launch_bounds__(256) ngemm_all(
    const float* __restrict__ H, const float* __restrict__ bilin,
    const float* __restrict__ Wrel, const float* __restrict__ Wroot,
    const float* __restrict__ bias, __half* __restrict__ hbhi,
    __half* __restrict__ hblo, float* __restrict__ HW,
    float* __restrict__ agg, int relu, int N) {
    __shared__ float Ws[64][64];
    __shared__ float Is[32][65];
    const int tid  = threadIdx.x;
    const int row0 = blockIdx.x * 32;
    const int o    = blockIdx.y;

    const float* W = (o == 0) ? bilin : (o < 4) ? Wrel + (size_t)(o - 1) * 4096 : Wroot;
    const int act = (o > 0) ? relu : 0;

    for (int i = tid; i < 64 * 64; i += 256) Ws[i >> 6][i & 63] = W[i];
    for (int i = tid; i < 32 * 64; i += 256) {
        float v = H[(size_t)(row0 + (i >> 6)) * 64 + (i & 63)];
        Is[i >> 6][i & 63] = act ? fmaxf(v, 0.f) : v;
    }
    __syncthreads();

    const int c  = tid & 63;
    const int r0 = tid >> 6;
    float acc[8];
    float bv = (o == 4) ? bias[c] : 0.f;
#pragma unroll
    for (int i = 0; i < 8; i++) acc[i] = bv;
#pragma unroll
    for (int k = 0; k < 64; k++) {
        float w = Ws[k][c];
#pragma unroll
        for (int i = 0; i < 8; i++) acc[i] += Is[r0 + i * 4][k] * w;
    }

    if (o == 0) {
#pragma unroll
        for (int i = 0; i < 8; i++) {
            size_t idx = (size_t)(row0 + r0 + i * 4) * 64 + c;
            __half h = __float2half_rn(acc[i]);
            hbhi[idx] = h;
            hblo[idx] = __float2half_rn(acc[i] - __half2float(h));
        }
    } else if (o < 4) {
        float* Out = HW + (size_t)(o - 1) * N * 64;
#pragma unroll
        for (int i = 0; i < 8; i++)
            Out[(size_t)(row0 + r0 + i * 4) * 64 + c] = acc[i];
    } else {
#pragma unroll
        for (int i = 0; i < 8; i++)
            agg[(size_t)(row0 + r0 + i * 4) * 64 + c] = acc[i];
    }
}

// ---------------- HMMA big GEMM: C = (Ahi + Alo) @ Bhi^T --------------------
// 128x128 CTA tile, 256 thr (8 warps: 4m x 2n), warp tile 32x64, 2 terms.
// SMEM: 3 tiles (Ahi, Alo, Bhi), 128B rows XOR-swizzled -> 48KB, 2 CTA/SM.
#define TILEB 16384
#define SM_TOT (3 * TILEB)

__device__ __forceinline__ uint32_t smem_u32(const void* p) {
    uint32_t a;
    asm("{ .reg .u64 t; cvta.to.shared.u64 t, %1; cvt.u32.u64 %0, t; }" : "=r"(a) : "l"(p));
    return a;
}
__device__ __forceinline__ void ldm_x4(uint32_t& r0, uint32_t& r1, uint32_t& r2,
                                       uint32_t& r3, uint32_t addr) {
    asm volatile("ldmatrix.sync.aligned.m8n8.x4.shared.b16 {%0,%1,%2,%3}, [%4];"
                 : "=r"(r0), "=r"(r1), "=r"(r2), "=r"(r3) : "r"(addr));
}
__device__ __forceinline__ void mma16816(float* c, const uint32_t* a,
                                         uint32_t b0, uint32_t b1) {
    asm volatile(
        "mma.sync.aligned.m16n8k16.row.col.f32.f16.f16.f32 "
        "{%0,%1,%2,%3}, {%4,%5,%6,%7}, {%8,%9}, {%0,%1,%2,%3};"
        : "+f"(c[0]), "+f"(c[1]), "+f"(c[2]), "+f"(c[3])
        : "r"(a[0]), "r"(a[1]), "r"(a[2]), "r"(a[3]), "r"(b0), "r"(b1));
}

__global__ void __launch_bounds__(256, 2) zgemm_mma(
    const __half* __restrict__ Ahi, const __half* __restrict__ Alo,
    const __half* __restrict__ Bhi, float* __restrict__ C, int N) {
    extern __shared__ __align__(16) char smem[];
    const int tid = threadIdx.x;
    const int m0 = blockIdx.y * 128, n0 = blockIdx.x * 128;

    // cooperative tile loads: 128 rows x 64 halfs (128B) per array, swizzled.
    {
        const int row = tid >> 1;
        const int cu  = (tid & 1) * 4;
        const int r7  = row & 7;
        const __half* gA0 = Ahi + (size_t)(m0 + row) * 64 + (tid & 1) * 32;
        const __half* gA1 = Alo + (size_t)(m0 + row) * 64 + (tid & 1) * 32;
        const __half* gB0 = Bhi + (size_t)(n0 + row) * 64 + (tid & 1) * 32;
        char* s = smem + row * 128;
#pragma unroll
        for (int i = 0; i < 4; i++) {
            int off = ((cu + i) ^ r7) << 4;
            *(uint4*)(s + 0 * TILEB + off) = *(const uint4*)(gA0 + i * 8);
            *(uint4*)(s + 1 * TILEB + off) = *(const uint4*)(gA1 + i * 8);
            *(uint4*)(s + 2 * TILEB + off) = *(const uint4*)(gB0 + i * 8);
        }
    }
    __syncthreads();

    const int lane = tid & 31;
    const int wid  = tid >> 5;
    const int wm   = (wid & 3) * 32;
    const int wn   = (wid >> 2) * 64;
    const uint32_t sb = smem_u32(smem);

    const int a_row = wm + (lane & 15);
    const int a_r7  = a_row & 7;
    const int au    = lane >> 4;
    const uint32_t abase_row = sb + a_row * 128;
    const int b_row = wn + (lane & 7) + (((lane >> 4) & 1) << 3);
    const int b_r7  = b_row & 7;
    const int bu    = (lane >> 3) & 1;
    const uint32_t bbase_row = sb + 2 * TILEB + b_row * 128;

    float acc[16][4];
#pragma unroll
    for (int i = 0; i < 16; i++)
#pragma unroll
        for (int j = 0; j < 4; j++) acc[i][j] = 0.f;

#pragma unroll
    for (int kc = 0; kc < 4; kc++) {
        const uint32_t aoffk = ((((kc << 1) + au) ^ a_r7) << 4);
        const uint32_t boffk = ((((kc << 1) + bu) ^ b_r7) << 4);
        uint32_t Ah[8], Al[8];
        ldm_x4(Ah[0], Ah[1], Ah[2], Ah[3], abase_row + aoffk);
        ldm_x4(Ah[4], Ah[5], Ah[6], Ah[7], abase_row + aoffk + 16 * 128);
        ldm_x4(Al[0], Al[1], Al[2], Al[3], abase_row + TILEB + aoffk);
        ldm_x4(Al[4], Al[5], Al[6], Al[7], abase_row + TILEB + aoffk + 16 * 128);
#pragma unroll
        for (int nt = 0; nt < 4; nt++) {
            uint32_t bh[4];
            ldm_x4(bh[0], bh[1], bh[2], bh[3], bbase_row + boffk + nt * 16 * 128);
            const int n0i = 2 * nt;
            // term Ahi*Bhi
            mma16816(acc[n0i],         Ah,     bh[0], bh[1]);
            mma16816(acc[n0i + 1],     Ah,     bh[2], bh[3]);
            mma16816(acc[8 + n0i],     Ah + 4, bh[0], bh[1]);
            mma16816(acc[8 + n0i + 1], Ah + 4, bh[2], bh[3]);
            // term Alo*Bhi
            mma16816(acc[n0i],         Al,     bh[0], bh[1]);
            mma16816(acc[n0i + 1],     Al,     bh[2], bh[3]);
            mma16816(acc[8 + n0i],     Al + 4, bh[0], bh[1]);
            mma16816(acc[8 + n0i + 1], Al + 4, bh[2], bh[3]);
        }
    }

    const int er = lane >> 2;
    const int ec = (lane & 3) * 2;
#pragma unroll
    for (int mi = 0; mi < 2; mi++)
#pragma unroll
        for (int ni = 0; ni < 8; ni++) {
            float* f = acc[mi * 8 + ni];
            size_t r = (size_t)(m0 + wm + mi * 16 + er);
            int col = n0 + wn + ni * 8 + ec;
            *(float2*)(C + r * N + col)       = make_float2(f[0], f[1]);
            *(float2*)(C + (r + 8) * N + col) = make_float2(f[2], f[3]);
        }
}

// ---------------- fused edge gather + scatter (16 lanes/edge, v4 red) -------
__global__ void edge_fused(const float* __restrict__ Z, const float* __restrict__ HW,
                           const int* __restrict__ row, const int* __restrict__ col,
                           const int* __restrict__ et, const float* __restrict__ ev,
                           float* __restrict__ agg, int E, int N) {
    int gi  = blockIdx.x * blockDim.x + threadIdx.x;
    int e   = gi >> 4;
    int sub = threadIdx.x & 15;
    if (e >= E) return;
    int r = row[e], c = col[e], t = et[e];
    float av = Z[(size_t)r * N + c] * ev[e];
    float4 m = ((const float4*)(HW + ((size_t)t * N + c) * 64))[sub];
    float* dst = agg + (size_t)r * 64 + sub * 4;
    asm volatile("red.global.add.v4.f32 [%0], {%1, %2, %3, %4};"
                 :: "l"(dst), "f"(m.x * av), "f"(m.y * av),
                    "f"(m.z * av), "f"(m.w * av) : "memory");
}

// ---------------- layernorm (+ fp16 hi of output) ----------------------------
__global__ void ln_split(const float* __restrict__ In, const float* __restrict__ g,
                         const float* __restrict__ b, float* __restrict__ Out,
                         __half2* __restrict__ hhi, int N) {
    int wrow = (blockIdx.x * blockDim.x + threadIdx.x) >> 5;
    int lane = threadIdx.x & 31;
    if (wrow >= N) return;
    float2 v = ((const float2*)(In + (size_t)wrow * 64))[lane];
    float s = v.x + v.y;
#pragma unroll
    for (int o = 16; o; o >>= 1) s += __shfl_xor_sync(0xffffffffu, s, o);
    float mu = s * (1.f / 64.f);
    float dx = v.x - mu, dy = v.y - mu;
    float q = dx * dx + dy * dy;
#pragma unroll
    for (int o = 16; o; o >>= 1) q += __shfl_xor_sync(0xffffffffu, q, o);
    float inv = rsqrtf(q * (1.f / 64.f) + 1e-5f);
    float2 gg = ((const float2*)g)[lane];
    float2 bb = ((const float2*)b)[lane];
    float ox = dx * inv * gg.x + bb.x;
    float oy = dy * inv * gg.y + bb.y;
    ((float2*)(Out + (size_t)wrow * 64))[lane] = make_float2(ox, oy);
    hhi[wrow * 32 + lane] = __halves2half2(__float2half_rn(ox), __float2half_rn(oy));
}

// ---------------------------------------------------------------------------
extern "C" void kernel_launch(void* const* d_in, const int* in_sizes, int n_in,
                              void* d_out, int out_size) {
    const float* x       = (const float*)d_in[0];
    const float* emb     = (const float*)d_in[1];
    const float* bilin   = (const float*)d_in[2];
    const float* eval    = (const float*)d_in[3];
    const float* W_root  = (const float*)d_in[4];
    const float* W_rel   = (const float*)d_in[5];
    const float* bias    = (const float*)d_in[6];
    const float* ln_g    = (const float*)d_in[7];
    const float* ln_b    = (const float*)d_in[8];
    const int*   erow    = (const int*)d_in[9];
    const int*   ecol    = (const int*)d_in[10];
    const int*   etype   = (const int*)d_in[11];

    const int NX = in_sizes[0] / D;
    const int NE = in_sizes[1] / D;
    const int N  = NX + NE;
    const int E  = in_sizes[3];

    float* out   = (float*)d_out;
    float* Hout  = out;
    float* Zbase = out + (size_t)N * D;

    float *H, *HW, *agg;
    uint2 *hbhi, *hblo, *hhi;
    cudaGetSymbolAddress((void**)&H,    g_H);
    cudaGetSymbolAddress((void**)&HW,   g_HW);
    cudaGetSymbolAddress((void**)&agg,  g_agg);
    cudaGetSymbolAddress((void**)&hbhi, g_hbhi);
    cudaGetSymbolAddress((void**)&hblo, g_hblo);
    cudaGetSymbolAddress((void**)&hhi,  g_hhi);

    cudaFuncSetAttribute(zgemm_mma, cudaFuncAttributeMaxDynamicSharedMemorySize, SM_TOT);

    // H = concat(x, emb) + fp16 hi
    {
        int total = N * D;
        int blocks = (total / 4 + 255) / 256;
        concat_split<<<blocks, 256>>>(x, emb, H, hhi, NX * D, total);
    }

    dim3 zgrid(N / 128, N / 128);
    dim3 ngrid(N / 32, 5);
    const int edge_blocks = (E * 16 + 255) / 256;
    const int ln_blocks   = (N * 32 + 255) / 256;

    for (int l = 0; l < 3; l++) {
        float* Zl   = Zbase + (size_t)l * N * N;
        float* aggl = (l < 2) ? agg : Hout;
        int relu = (l > 0) ? 1 : 0;

        // Hb(hi/lo) + HW[0..2] + agg (parallel over outputs)
        ngemm_all<<<ngrid, 256>>>(H, bilin + (size_t)l * D * D,
                                  W_rel + (size_t)l * 3 * D * D,
                                  W_root + (size_t)l * D * D,
                                  bias + (size_t)l * D,
                                  (__half*)hbhi, (__half*)hblo,
                                  HW, aggl, relu, N);
        // Z = (Hbhi + Hblo) @ Hhi^T via HMMA 2-term
        zgemm_mma<<<zgrid, 256, SM_TOT>>>((const __half*)hbhi, (const __half*)hblo,
                                          (const __half*)hhi, Zl, N);
        // agg[row] += HW[etype, col] * (Z[row,col] * ev)
        edge_fused<<<edge_blocks, 256>>>(Zl, HW, erow, ecol, etype, eval, aggl, E, N);

        if (l < 2)
            ln_split<<<ln_blocks, 256>>>(aggl, ln_g + (size_t)l * D, ln_b + (size_t)l * D,
                                         H, (__half2*)hhi, N);
    }
}